// round 16
// baseline (speedup 1.0000x reference)
#include <cuda_runtime.h>

#define HD      768
#define SEQ     256
#define BATCH   4
#define ROWS    1024
#define NP      54
#define THRESH  0.5f
#define ROWOUT  (SEQ * NP)          // 13824

typedef unsigned long long u64;

// Scratch (device globals — no allocation allowed)
__device__ float g_part[12 * ROWS];       // per-ntile partial span dots
__device__ float g_habC[ROWS * 2 * HD];   // COMPACT: [slot][ha(768) | hb(768)]
__device__ int   g_rows[ROWS];            // slot -> row
__device__ int   g_pA[BATCH * SEQ * SEQ];   // (si<<10) | sj
__device__ int   g_pOut[BATCH * SEQ * SEQ]; // rowi*256 + j
__device__ int   g_cnt;
__device__ int   g_nrows;
__device__ float g_dummy;

__device__ __forceinline__ void fma2(u64& d, u64 a, u64 b) {
    asm("fma.rn.f32x2 %0, %1, %2, %0;" : "+l"(d) : "l"(a), "l"(b));
}
__device__ __forceinline__ u64 dup2(float a) {
    u64 r; asm("mov.b64 %0, {%1, %1};" : "=l"(r) : "f"(a)); return r;
}
__device__ __forceinline__ void unpack2(float& lo, float& hi, u64 v) {
    asm("mov.b64 {%0, %1}, %2;" : "=f"(lo), "=f"(hi) : "l"(v));
}

// ---------------------------------------------------------------------------
// GEMM (full-K, fused epilogue): per CTA compute c = x@W1s^T for a 64x64 tile
// over the FULL K=768, then reduce sum_n relu(c + b1s)*W2s[0] -> g_part.
// grid (12,16) = 192 CTAs, 256 threads, occ 3 (6 warps/SMSP).
// 8m x 2n per thread via m-pair FFMA2. Output zero-fill trickled in.
// ---------------------------------------------------------------------------
#define GM 64
#define GN 64
#define GK 16
#define GLD 68

__global__ void __launch_bounds__(256, 3) gemm_kernel(
    const float* __restrict__ X,
    const float* __restrict__ W1s,
    const float* __restrict__ b1s,
    const float* __restrict__ W2s,
    float* __restrict__ out)
{
    __shared__ __align__(16) float As[2][GK * GLD];
    __shared__ __align__(16) float Bs[2][GK * GLD];
    __shared__ float sp[GM * 33];

    const int tid = threadIdx.x;
    const int n0 = blockIdx.x * GN;
    const int m0 = blockIdx.y * GM;

    // loader mapping: row am (0..63), k-quad akq
    const int am  = tid >> 2;
    const int akq = (tid & 3) * 4;
    const float* gA = X   + (m0 + am) * HD + akq;
    const float* gB = W1s + (n0 + am) * HD + akq;

    // compute mapping: rows tyg*8..+7, cols txg*2, txg*2+1
    const int tyg = tid >> 5;       // 0..7
    const int txg = tid & 31;       // 0..31

    // zero-fill: 72 float4 per thread over the 48 iterations
    const int ctaid = blockIdx.y * 12 + blockIdx.x;      // 0..191
    float4* o4 = (float4*)out + (size_t)ctaid * 18432 + tid;
    const float4 z4 = make_float4(0.f, 0.f, 0.f, 0.f);

    u64 acc[2][4];
    #pragma unroll
    for (int n = 0; n < 2; n++)
        #pragma unroll
        for (int mp = 0; mp < 4; mp++) acc[n][mp] = 0ull;

    float4 ra, rb;

    // prologue: load it0, store buf0, load it1
    ra = *(const float4*)gA;
    rb = *(const float4*)gB;
    {
        As[0][(akq+0)*GLD + am] = ra.x;  As[0][(akq+1)*GLD + am] = ra.y;
        As[0][(akq+2)*GLD + am] = ra.z;  As[0][(akq+3)*GLD + am] = ra.w;
        Bs[0][(akq+0)*GLD + am] = rb.x;  Bs[0][(akq+1)*GLD + am] = rb.y;
        Bs[0][(akq+2)*GLD + am] = rb.z;  Bs[0][(akq+3)*GLD + am] = rb.w;
    }
    ra = *(const float4*)(gA + GK);
    rb = *(const float4*)(gB + GK);

    const int NITER = HD / GK;   // 48

    for (int it = 0; it < NITER; it++) {
        __syncthreads();
        const int cb = it & 1;

        if (it < 36) {                       // 2 zero stores per iter
            o4[(2 * it + 0) * 256] = z4;
            o4[(2 * it + 1) * 256] = z4;
        }

        #pragma unroll
        for (int k = 0; k < GK; k++) {
            ulonglong2 a01 = *(const ulonglong2*)&As[cb][k * GLD + tyg * 8];
            ulonglong2 a23 = *(const ulonglong2*)&As[cb][k * GLD + tyg * 8 + 4];
            float2 bf = *(const float2*)&Bs[cb][k * GLD + txg * 2];
            u64 b0 = dup2(bf.x);
            u64 b1 = dup2(bf.y);
            fma2(acc[0][0], a01.x, b0);  fma2(acc[0][1], a01.y, b0);
            fma2(acc[0][2], a23.x, b0);  fma2(acc[0][3], a23.y, b0);
            fma2(acc[1][0], a01.x, b1);  fma2(acc[1][1], a01.y, b1);
            fma2(acc[1][2], a23.x, b1);  fma2(acc[1][3], a23.y, b1);
        }

        if (it + 1 < NITER) {
            const int sb = (it + 1) & 1;
            As[sb][(akq+0)*GLD + am] = ra.x;  As[sb][(akq+1)*GLD + am] = ra.y;
            As[sb][(akq+2)*GLD + am] = ra.z;  As[sb][(akq+3)*GLD + am] = ra.w;
            Bs[sb][(akq+0)*GLD + am] = rb.x;  Bs[sb][(akq+1)*GLD + am] = rb.y;
            Bs[sb][(akq+2)*GLD + am] = rb.z;  Bs[sb][(akq+3)*GLD + am] = rb.w;
            if (it + 2 < NITER) {
                int ko = (it + 2) * GK;
                ra = *(const float4*)(gA + ko);
                rb = *(const float4*)(gB + ko);
            }
        }
    }

    // epilogue: relu(c + b1s)*W2s[0], reduce over this tile's 64 n
    float cv[8][2];
    #pragma unroll
    for (int n = 0; n < 2; n++)
        #pragma unroll
        for (int mp = 0; mp < 4; mp++)
            unpack2(cv[2*mp][n], cv[2*mp+1][n], acc[n][mp]);

    const int nc = n0 + txg * 2;
    const float b10 = b1s[nc],  b11 = b1s[nc + 1];
    const float w20 = W2s[nc],  w21 = W2s[nc + 1];

    __syncthreads();               // As/Bs dead; sp phase begins
    #pragma unroll
    for (int r = 0; r < 8; r++) {
        float p = fmaxf(cv[r][0] + b10, 0.f) * w20
                + fmaxf(cv[r][1] + b11, 0.f) * w21;
        sp[(tyg * 8 + r) * 33 + txg] = p;
    }
    __syncthreads();
    if (tid < GM) {
        float s = 0.f;
        #pragma unroll
        for (int t = 0; t < 32; t++) s += sp[tid * 33 + t];
        g_part[blockIdx.x * ROWS + m0 + tid] = s;
    }
}

// ---------------------------------------------------------------------------
// CANDCOMPACT: single block, 1024 threads. Reads g_part (48KB), thresholds,
// builds row list + slot map + the (si,sj)-encoded pair list, all in smem.
// ---------------------------------------------------------------------------
__global__ void __launch_bounds__(1024) candcompact_kernel(
    const float* __restrict__ b2s)
{
    __shared__ int fc[ROWS];
    __shared__ int sslot[ROWS];
    __shared__ int s_nr, s_cnt;

    const int t = threadIdx.x;     // = row
    float s = b2s[0];
    #pragma unroll
    for (int nt = 0; nt < 12; nt++) s += g_part[nt * ROWS + t];
    const int c = (s > THRESH) ? 1 : 0;
    fc[t] = c;
    if (t == 0) { s_nr = 0; s_cnt = 0; }
    __syncthreads();

    if (c) {
        int r = atomicAdd(&s_nr, 1);
        g_rows[r] = t;
        sslot[t] = r;
    }
    __syncthreads();

    if (c) {
        const int b0 = t & ~255;
        const int i  = t & 255;
        int cnt = 0;
        for (int j = 0; j < SEQ; j++)
            if (fc[b0 + j] && j != i) cnt++;
        if (cnt) {
            int p = atomicAdd(&s_cnt, cnt);
            const int si = sslot[t];
            for (int j = 0; j < SEQ; j++)
                if (fc[b0 + j] && j != i) {
                    g_pA[p]   = (si << 10) | sslot[b0 + j];
                    g_pOut[p] = t * SEQ + j;
                    p++;
                }
        }
    }
    __syncthreads();
    if (t == 0) { g_cnt = s_cnt; g_nrows = s_nr; }
}

// ---------------------------------------------------------------------------
// HAB: warp per (slot, column), float4 loads, compact output.
// First 41 blocks also warm Wp2 into L2 for the pair kernel.
// ---------------------------------------------------------------------------
__global__ void __launch_bounds__(256) hab_kernel(
    const float* __restrict__ X,
    const float* __restrict__ Wp1,
    const float* __restrict__ Wp2)
{
    // L2-warm Wp2 (10368 float4): first 41 blocks, 1 load each
    {
        int e = blockIdx.x * 256 + threadIdx.x;
        if (e < NP * HD / 4) {
            float4 wv = ((const float4*)Wp2)[e];
            float s = wv.x + wv.y + wv.z + wv.w;
            if (s == 123456.789f) g_dummy = s;   // never true; keeps the load
        }
    }

    const int lane   = threadIdx.x & 31;
    const int gwarp  = blockIdx.x * 8 + (threadIdx.x >> 5);
    const int nwarps = 1024 * 8;
    const int total  = g_nrows * 1536;

    for (int item = gwarp; item < total; item += nwarps) {
        const int rs  = item / 1536;
        const int c   = item - rs * 1536;
        const int row = g_rows[rs];
        const float4* xr = (const float4*)(X + row * HD);
        const float* wr  = (c < HD) ? (Wp1 + (size_t)c * (2 * HD))
                                    : (Wp1 + (size_t)(c - HD) * (2 * HD) + HD);
        const float4* w4 = (const float4*)wr;
        float s = 0.f;
        #pragma unroll
        for (int t = 0; t < HD / 128; t++) {
            int k = lane + 32 * t;
            float4 xv = __ldg(&xr[k]);
            float4 wv = __ldg(&w4[k]);
            s += xv.x * wv.x + xv.y * wv.y + xv.z * wv.z + xv.w * wv.w;
        }
        #pragma unroll
        for (int o = 16; o > 0; o >>= 1)
            s += __shfl_xor_sync(0xffffffffu, s, o);
        if (lane == 0) g_habC[(size_t)rs * (2 * HD) + c] = s;
    }
}

// ---------------------------------------------------------------------------
// PAIR: block per pair (grid-stride). All-float4, high MLP (unchanged, R15).
// ---------------------------------------------------------------------------
__global__ void pair_kernel(
    const float* __restrict__ bp1,
    const float* __restrict__ Wp2,
    const float* __restrict__ bp2,
    float* __restrict__ out)
{
    __shared__ float4 v4[HD / 4];          // 192
    const int tid  = threadIdx.x;
    const int warp = tid >> 5;
    const int lane = tid & 31;
    const int cnt  = g_cnt;
    const float4* w2_4 = (const float4*)Wp2;
    const float4* b1_4 = (const float4*)bp1;

    for (int p = blockIdx.x; p < cnt; p += gridDim.x) {
        const int ab   = g_pA[p];
        const int code = g_pOut[p];
        const int si   = ab >> 10;
        const int sj   = ab & 1023;

        __syncthreads();
        if (tid < HD / 4) {
            const float4* ha = (const float4*)g_habC + (size_t)si * 384;
            const float4* hb = (const float4*)g_habC + (size_t)sj * 384 + 192;
            float4 a = ha[tid], b = hb[tid], c = __ldg(&b1_4[tid]);
            float4 r;
            r.x = fmaxf(a.x + b.x + c.x, 0.f);
            r.y = fmaxf(a.y + b.y + c.y, 0.f);
            r.z = fmaxf(a.z + b.z + c.z, 0.f);
            r.w = fmaxf(a.w + b.w + c.w, 0.f);
            v4[tid] = r;
        }
        __syncthreads();

        float acc[7];
        #pragma unroll
        for (int q = 0; q < 7; q++) acc[q] = 0.f;

        #pragma unroll
        for (int t = 0; t < HD / 128; t++) {
            int k = lane + 32 * t;
            float4 vv = v4[k];
            #pragma unroll
            for (int q = 0; q < 7; q++) {
                int pp = warp + 8 * q;
                if (pp < NP) {
                    float4 wv = __ldg(&w2_4[pp * (HD / 4) + k]);
                    acc[q] += vv.x * wv.x + vv.y * wv.y + vv.z * wv.z + vv.w * wv.w;
                }
            }
        }
        #pragma unroll
        for (int q = 0; q < 7; q++) {
            #pragma unroll
            for (int off = 16; off > 0; off >>= 1)
                acc[q] += __shfl_xor_sync(0xffffffffu, acc[q], off);
        }
        if (lane == 0) {
            float* o = out + (size_t)code * NP;
            #pragma unroll
            for (int q = 0; q < 7; q++) {
                int pp = warp + 8 * q;
                if (pp < NP) o[pp] = acc[q] + bp2[pp];
            }
        }
    }
}

// ---------------------------------------------------------------------------
extern "C" void kernel_launch(void* const* d_in, const int* in_sizes, int n_in,
                              void* d_out, int out_size)
{
    const float* x   = (const float*)d_in[0];
    const float* W1s = (const float*)d_in[1];
    const float* b1s = (const float*)d_in[2];
    const float* W2s = (const float*)d_in[3];
    const float* b2s = (const float*)d_in[4];
    const float* Wp1 = (const float*)d_in[5];
    const float* bp1 = (const float*)d_in[6];
    const float* Wp2 = (const float*)d_in[7];
    const float* bp2 = (const float*)d_in[8];
    float* out = (float*)d_out;

    // 1) full-K fused GEMM (span partials) + trickled output zero-fill
    dim3 g1(HD / GN, ROWS / GM);                 // (12, 16) = 192 CTAs
    gemm_kernel<<<g1, 256>>>(x, W1s, b1s, W2s, out);

    // 2) threshold + row/slot lists + pair list (one block, 48KB read)
    candcompact_kernel<<<1, 1024>>>(b2s);

    // 3) ha/hb -> compact slot buffer (+ Wp2 L2 warm)
    hab_kernel<<<1024, 256>>>(x, Wp1, Wp2);

    // 4) pair logits, all-float4 high-MLP
    pair_kernel<<<2048, 256>>>(bp1, Wp2, bp2, out);
}

// round 17
// speedup vs baseline: 1.2948x; 1.2948x over previous
#include <cuda_runtime.h>

#define HD      768
#define SEQ     256
#define BATCH   4
#define ROWS    1024
#define NP      54
#define THRESH  0.5f
#define ROWOUT  (SEQ * NP)          // 13824
#define CROWS   (ROWS * HD)         // 786432 floats per split buffer
#define NSPLIT  6

typedef unsigned long long u64;

// Scratch (device globals — no allocation allowed)
__device__ float g_c[NSPLIT * CROWS];     // split-K partials (18.9 MB)
__device__ float g_habC[ROWS * 2 * HD];   // COMPACT: [slot][ha(768) | hb(768)]
__device__ int   g_cand[ROWS];
__device__ int   g_rows[ROWS];            // slot -> row
__device__ int   g_slot[ROWS];            // row -> slot
__device__ int   g_pA[BATCH * SEQ * SEQ];   // (si<<10) | sj
__device__ int   g_pOut[BATCH * SEQ * SEQ]; // rowi*256 + j
__device__ int   g_cnt;
__device__ int   g_nrows;
__device__ float g_dummy;

__device__ __forceinline__ void fma2(u64& d, u64 a, u64 b) {
    asm("fma.rn.f32x2 %0, %1, %2, %0;" : "+l"(d) : "l"(a), "l"(b));
}
__device__ __forceinline__ u64 dup2(float a) {
    u64 r; asm("mov.b64 %0, {%1, %1};" : "=l"(r) : "f"(a)); return r;
}
__device__ __forceinline__ void unpack2(float& lo, float& hi, u64 v) {
    asm("mov.b64 {%0, %1}, %2;" : "=f"(lo), "=f"(hi) : "l"(v));
}

// ---------------------------------------------------------------------------
// GEMM: partial c = x[:, ks:ks+128] @ W1s[:, ks:ks+128]^T  -> g_c[split]
// BM=128, BN=128, BK=16, split-K=6, grid (6,8,6)=288 CTAs (single wave, occ2)
// 8m x 8n per thread: 4 LDS.128 -> 64 MACs (1 B/MAC; crossbar == FFMA2 floor)
// Trickles the 56.6MB output zero-fill through the k-loop.
// ---------------------------------------------------------------------------
#define BM 128
#define BN 128
#define BK 16
#define KSPLIT 128
#define LDA 132

__global__ void __launch_bounds__(256, 2) gemm_kernel(
    const float* __restrict__ X,
    const float* __restrict__ W1s,
    float* __restrict__ out)
{
    __shared__ __align__(16) float As[2][BK * LDA];
    __shared__ __align__(16) float Bs[2][BK * LDA];

    const int tid = threadIdx.x;
    const int n0 = blockIdx.x * BN;
    const int m0 = blockIdx.y * BM;
    const int ks = blockIdx.z * KSPLIT;
    const int ty = tid >> 4;          // 0..15 : rows ty*8..+7
    const int tx = tid & 15;          // 0..15 : cols tx*8..+7

    const int ctaid = blockIdx.z * 48 + blockIdx.y * 6 + blockIdx.x;  // 0..287
    if (ctaid == 0 && tid == 0) { g_nrows = 0; g_cnt = 0; }
    float4* o4 = (float4*)out + ctaid * 12288 + tid;

    const int am  = tid >> 2;         // 0..63 (rows am, am+64 for both A and B)
    const int akq = (tid & 3) * 4;    // k quad

    const float* gA0 = X   + (m0 + am) * HD + ks + akq;
    const float* gA1 = gA0 + 64 * HD;
    const float* gB0 = W1s + (n0 + am) * HD + ks + akq;
    const float* gB1 = gB0 + 64 * HD;

    u64 acc[8][4];   // acc[n][mp]: col tx*8+n, row-pair (2mp, 2mp+1)
    #pragma unroll
    for (int n = 0; n < 8; n++)
        #pragma unroll
        for (int mp = 0; mp < 4; mp++) acc[n][mp] = 0ull;

    float4 ra0, ra1, rb0, rb1;

    ra0 = *(const float4*)gA0;
    ra1 = *(const float4*)gA1;
    rb0 = *(const float4*)gB0;
    rb1 = *(const float4*)gB1;
    {
        #pragma unroll
        for (int q = 0; q < 4; q++) {
            As[0][(akq+q)*LDA + am]      = (&ra0.x)[q];
            As[0][(akq+q)*LDA + am + 64] = (&ra1.x)[q];
            Bs[0][(akq+q)*LDA + am]      = (&rb0.x)[q];
            Bs[0][(akq+q)*LDA + am + 64] = (&rb1.x)[q];
        }
    }
    ra0 = *(const float4*)(gA0 + BK);
    ra1 = *(const float4*)(gA1 + BK);
    rb0 = *(const float4*)(gB0 + BK);
    rb1 = *(const float4*)(gB1 + BK);

    const int NITER = KSPLIT / BK;   // 8
    const float4 z4 = make_float4(0.f, 0.f, 0.f, 0.f);

    for (int it = 0; it < NITER; it++) {
        __syncthreads();
        const int cb = it & 1;

        // trickle 6 zero stores per iteration (48 total per thread)
        #pragma unroll
        for (int q = 0; q < 6; q++)
            o4[(it * 6 + q) * 256] = z4;

        #pragma unroll
        for (int k = 0; k < BK; k++) {
            ulonglong2 a01 = *(const ulonglong2*)&As[cb][k * LDA + ty * 8];
            ulonglong2 a23 = *(const ulonglong2*)&As[cb][k * LDA + ty * 8 + 4];
            float4 bf0 = *(const float4*)&Bs[cb][k * LDA + tx * 8];
            float4 bf1 = *(const float4*)&Bs[cb][k * LDA + tx * 8 + 4];
            u64 ap[4] = {a01.x, a01.y, a23.x, a23.y};
            u64 bd[8] = {dup2(bf0.x), dup2(bf0.y), dup2(bf0.z), dup2(bf0.w),
                         dup2(bf1.x), dup2(bf1.y), dup2(bf1.z), dup2(bf1.w)};
            #pragma unroll
            for (int n = 0; n < 8; n++)
                #pragma unroll
                for (int mp = 0; mp < 4; mp++)
                    fma2(acc[n][mp], ap[mp], bd[n]);
        }

        if (it + 1 < NITER) {
            const int sb = (it + 1) & 1;
            #pragma unroll
            for (int q = 0; q < 4; q++) {
                As[sb][(akq+q)*LDA + am]      = (&ra0.x)[q];
                As[sb][(akq+q)*LDA + am + 64] = (&ra1.x)[q];
                Bs[sb][(akq+q)*LDA + am]      = (&rb0.x)[q];
                Bs[sb][(akq+q)*LDA + am + 64] = (&rb1.x)[q];
            }
            if (it + 2 < NITER) {
                int ko = (it + 2) * BK;
                ra0 = *(const float4*)(gA0 + ko);
                ra1 = *(const float4*)(gA1 + ko);
                rb0 = *(const float4*)(gB0 + ko);
                rb1 = *(const float4*)(gB1 + ko);
            }
        }
    }

    // epilogue: write raw partials (8 rows x 8 cols per thread)
    float* cb = g_c + blockIdx.z * CROWS;
    #pragma unroll
    for (int mp = 0; mp < 4; mp++) {
        float lo[8], hi[8];
        #pragma unroll
        for (int n = 0; n < 8; n++) unpack2(lo[n], hi[n], acc[n][mp]);
        int mA = m0 + ty * 8 + 2 * mp;
        *(float4*)&cb[(size_t)mA * HD + n0 + tx * 8]     = make_float4(lo[0], lo[1], lo[2], lo[3]);
        *(float4*)&cb[(size_t)mA * HD + n0 + tx * 8 + 4] = make_float4(lo[4], lo[5], lo[6], lo[7]);
        *(float4*)&cb[(size_t)(mA+1) * HD + n0 + tx * 8]     = make_float4(hi[0], hi[1], hi[2], hi[3]);
        *(float4*)&cb[(size_t)(mA+1) * HD + n0 + tx * 8 + 4] = make_float4(hi[4], hi[5], hi[6], hi[7]);
    }
}

// ---------------------------------------------------------------------------
// CAND: warp per row, float4 loads, sums 6 split partials.
// ---------------------------------------------------------------------------
__global__ void __launch_bounds__(256) cand_kernel(
    const float* __restrict__ b1s,
    const float* __restrict__ W2s,
    const float* __restrict__ b2s)
{
    const int row  = (blockIdx.x * 256 + threadIdx.x) >> 5;
    const int lane = threadIdx.x & 31;
    const float4* b4 = (const float4*)b1s;
    const float4* w4 = (const float4*)W2s;
    float s = 0.f;
    #pragma unroll
    for (int t = 0; t < HD / 128; t++) {       // 6 rounds
        int k = lane + 32 * t;
        float4 a = ((const float4*)(g_c + (size_t)row * HD))[k];
        #pragma unroll
        for (int sp = 1; sp < NSPLIT; sp++) {
            float4 b = ((const float4*)(g_c + (size_t)sp * CROWS + (size_t)row * HD))[k];
            a.x += b.x; a.y += b.y; a.z += b.z; a.w += b.w;
        }
        float4 bb = __ldg(&b4[k]);
        float4 ww = __ldg(&w4[k]);
        s += fmaxf(a.x + bb.x, 0.f) * ww.x;
        s += fmaxf(a.y + bb.y, 0.f) * ww.y;
        s += fmaxf(a.z + bb.z, 0.f) * ww.z;
        s += fmaxf(a.w + bb.w, 0.f) * ww.w;
    }
    #pragma unroll
    for (int o = 16; o > 0; o >>= 1)
        s += __shfl_xor_sync(0xffffffffu, s, o);
    if (lane == 0) {
        int c = (s + b2s[0]) > THRESH ? 1 : 0;
        g_cand[row] = c;
        if (c) {
            int r = atomicAdd(&g_nrows, 1);
            g_rows[r] = row;
            g_slot[row] = r;
        }
    }
}

// ---------------------------------------------------------------------------
// HABCOMPACT: blocks 0-3 build the (si,sj)-encoded pair list; blocks 4-1027
// compute hab (warp per (slot,col), float4) AND warm Wp2 into L2.
// ---------------------------------------------------------------------------
__global__ void __launch_bounds__(256) habcompact_kernel(
    const float* __restrict__ X,
    const float* __restrict__ Wp1,
    const float* __restrict__ Wp2)
{
    if (blockIdx.x < 4) {
        __shared__ int fc[SEQ];
        const int b = blockIdx.x;
        const int t = threadIdx.x;
        fc[t] = g_cand[b * SEQ + t];
        __syncthreads();
        if (fc[t]) {
            const int i = t;
            const int si = g_slot[b * SEQ + i];
            int cnt = 0;
            for (int j = 0; j < SEQ; j++)
                if (fc[j] && j != i) cnt++;
            if (cnt) {
                int p = atomicAdd(&g_cnt, cnt);
                for (int j = 0; j < SEQ; j++)
                    if (fc[j] && j != i) {
                        g_pA[p]   = (si << 10) | g_slot[b * SEQ + j];
                        g_pOut[p] = (b * SEQ + i) * SEQ + j;
                        p++;
                    }
            }
        }
        return;
    }

    // L2-warm Wp2 (10368 float4): first 41 blocks, 1 load each
    {
        int e = (blockIdx.x - 4) * 256 + threadIdx.x;
        if (e < NP * HD / 4) {
            float4 wv = ((const float4*)Wp2)[e];
            float s = wv.x + wv.y + wv.z + wv.w;
            if (s == 123456.789f) g_dummy = s;   // never true; keeps the load
        }
    }

    const int lane   = threadIdx.x & 31;
    const int gwarp  = (blockIdx.x - 4) * 8 + (threadIdx.x >> 5);
    const int nwarps = 1024 * 8;
    const int total  = g_nrows * 1536;

    for (int item = gwarp; item < total; item += nwarps) {
        const int rs  = item / 1536;
        const int c   = item - rs * 1536;
        const int row = g_rows[rs];
        const float4* xr = (const float4*)(X + row * HD);
        const float* wr  = (c < HD) ? (Wp1 + (size_t)c * (2 * HD))
                                    : (Wp1 + (size_t)(c - HD) * (2 * HD) + HD);
        const float4* w4 = (const float4*)wr;
        float s = 0.f;
        #pragma unroll
        for (int t = 0; t < HD / 128; t++) {
            int k = lane + 32 * t;
            float4 xv = __ldg(&xr[k]);
            float4 wv = __ldg(&w4[k]);
            s += xv.x * wv.x + xv.y * wv.y + xv.z * wv.z + xv.w * wv.w;
        }
        #pragma unroll
        for (int o = 16; o > 0; o >>= 1)
            s += __shfl_xor_sync(0xffffffffu, s, o);
        if (lane == 0) g_habC[(size_t)rs * (2 * HD) + c] = s;
    }
}

// ---------------------------------------------------------------------------
// PAIR: block per pair (grid-stride). All-float4, high MLP (unchanged, R15).
// ---------------------------------------------------------------------------
__global__ void pair_kernel(
    const float* __restrict__ bp1,
    const float* __restrict__ Wp2,
    const float* __restrict__ bp2,
    float* __restrict__ out)
{
    __shared__ float4 v4[HD / 4];          // 192
    const int tid  = threadIdx.x;
    const int warp = tid >> 5;
    const int lane = tid & 31;
    const int cnt  = g_cnt;
    const float4* w2_4 = (const float4*)Wp2;
    const float4* b1_4 = (const float4*)bp1;

    for (int p = blockIdx.x; p < cnt; p += gridDim.x) {
        const int ab   = g_pA[p];
        const int code = g_pOut[p];
        const int si   = ab >> 10;
        const int sj   = ab & 1023;

        __syncthreads();
        if (tid < HD / 4) {
            const float4* ha = (const float4*)g_habC + (size_t)si * 384;
            const float4* hb = (const float4*)g_habC + (size_t)sj * 384 + 192;
            float4 a = ha[tid], b = hb[tid], c = __ldg(&b1_4[tid]);
            float4 r;
            r.x = fmaxf(a.x + b.x + c.x, 0.f);
            r.y = fmaxf(a.y + b.y + c.y, 0.f);
            r.z = fmaxf(a.z + b.z + c.z, 0.f);
            r.w = fmaxf(a.w + b.w + c.w, 0.f);
            v4[tid] = r;
        }
        __syncthreads();

        float acc[7];
        #pragma unroll
        for (int q = 0; q < 7; q++) acc[q] = 0.f;

        #pragma unroll
        for (int t = 0; t < HD / 128; t++) {
            int k = lane + 32 * t;
            float4 vv = v4[k];
            #pragma unroll
            for (int q = 0; q < 7; q++) {
                int pp = warp + 8 * q;
                if (pp < NP) {
                    float4 wv = __ldg(&w2_4[pp * (HD / 4) + k]);
                    acc[q] += vv.x * wv.x + vv.y * wv.y + vv.z * wv.z + vv.w * wv.w;
                }
            }
        }
        #pragma unroll
        for (int q = 0; q < 7; q++) {
            #pragma unroll
            for (int off = 16; off > 0; off >>= 1)
                acc[q] += __shfl_xor_sync(0xffffffffu, acc[q], off);
        }
        if (lane == 0) {
            float* o = out + (size_t)code * NP;
            #pragma unroll
            for (int q = 0; q < 7; q++) {
                int pp = warp + 8 * q;
                if (pp < NP) o[pp] = acc[q] + bp2[pp];
            }
        }
    }
}

// ---------------------------------------------------------------------------
extern "C" void kernel_launch(void* const* d_in, const int* in_sizes, int n_in,
                              void* d_out, int out_size)
{
    const float* x   = (const float*)d_in[0];
    const float* W1s = (const float*)d_in[1];
    const float* b1s = (const float*)d_in[2];
    const float* W2s = (const float*)d_in[3];
    const float* b2s = (const float*)d_in[4];
    const float* Wp1 = (const float*)d_in[5];
    const float* bp1 = (const float*)d_in[6];
    const float* Wp2 = (const float*)d_in[7];
    const float* bp2 = (const float*)d_in[8];
    float* out = (float*)d_out;

    // 1) split-K(6) 128x128 GEMM + fused output zero-fill + counter resets
    dim3 g1(HD / BN, ROWS / BM, NSPLIT);         // (6, 8, 6) = 288 CTAs
    gemm_kernel<<<g1, 256>>>(x, W1s, out);

    // 2) candidate mask + row/slot lists (float4, 6 partials)
    cand_kernel<<<ROWS / 8, 256>>>(b1s, W2s, b2s);

    // 3) pair-list compaction + hab + Wp2 L2-warm
    habcompact_kernel<<<1028, 256>>>(x, Wp1, Wp2);

    // 4) pair logits, all-float4 high-MLP
    pair_kernel<<<2048, 256>>>(bp1, Wp2, bp2, out);
}